// round 1
// baseline (speedup 1.0000x reference)
#include <cuda_runtime.h>

// ObservabilityWeightedMSE — fused single-pass weighted-MSE reduction.
// Inputs (metadata order): d_in[0]=predictions [500000,82] f32,
//                          d_in[1]=targets     [500000,82] f32,
//                          d_in[2]=inputs      [500000,400] f32
// Output: scalar f32 mean(raw_mse * final_weights).

#define THRESH 1e-4f
#define NCOLS 82
#define ROW_IN 400

__device__ double g_acc;

__global__ void zero_acc_kernel() { g_acc = 0.0; }

__global__ void finalize_kernel(float* out, long long total_elems) {
    out[0] = (float)(g_acc / (double)total_elems);
}

__global__ void __launch_bounds__(256)
wmse_kernel(const float* __restrict__ pred,
            const float* __restrict__ targ,
            const float* __restrict__ inp,
            int B)
{
    const int lane  = threadIdx.x & 31;
    const int warp  = threadIdx.x >> 5;
    const int gwarp = blockIdx.x * (blockDim.x >> 5) + warp;
    const int nwarp = gridDim.x * (blockDim.x >> 5);

    float acc = 0.0f;

    for (int r = gwarp; r < B; r += nwarp) {
        // ---- node "not below threshold" bits from the magnitude slice ----
        // magnitudes for node n are inputs[r, n*40 .. n*40+19] (20 floats = 5 float4).
        // below[n]  <=> max < THRESH <=> all 20 < THRESH
        // ok bit set <=> any element >= THRESH  (i.e. NOT below)
        const float* pin = inp + (size_t)r * ROW_IN;
        unsigned ok = 0;
        {
            // idx 0..49 maps to (node = idx/5, quad = idx%5); two iterations cover 50.
            int n0 = lane / 5, p0 = lane % 5;            // idx = lane (all 32 valid)
            float4 v0 = *(const float4*)(pin + n0 * 40 + p0 * 4);
            if (v0.x >= THRESH || v0.y >= THRESH || v0.z >= THRESH || v0.w >= THRESH)
                ok = 1u << n0;
            int idx1 = 32 + lane;
            if (idx1 < 50) {
                int n1 = idx1 / 5, p1 = idx1 % 5;
                float4 v1 = *(const float4*)(pin + n1 * 40 + p1 * 4);
                if (v1.x >= THRESH || v1.y >= THRESH || v1.z >= THRESH || v1.w >= THRESH)
                    ok |= 1u << n1;
            }
        }
        unsigned notbelow = __reduce_or_sync(0xffffffffu, ok);
        unsigned below    = (~notbelow) & 0x3FFu;
        // stage_cutoff = (first_idx + 1) * 4 = __ffs(below) * 4 ; no-below => never cut
        int cutoff = below ? (__ffs(below) << 2) : 1000;

        // ---- weighted MSE over 82 columns ----
        const float* pp = pred + (size_t)r * NCOLS;
        const float* pt = targ + (size_t)r * NCOLS;
        #pragma unroll
        for (int it = 0; it < 3; ++it) {
            int c = it * 32 + lane;
            if (c < NCOLS) {
                float d = pp[c] - pt[c];
                // spatial mask (PRIORITY_FACTOR = 5):
                //   first half  (c in [0,41)):  5 iff c % 4 == 0
                //   second half (j = c - 41):   5 iff j%4==3, or (j%4==0 and j != 40)
                bool five;
                int col;
                if (c < 41) {
                    col = c;
                    five = ((c & 3) == 0);
                } else {
                    int j = c - 41;
                    col = j;
                    five = ((j & 3) == 3) || (((j & 3) == 0) && (j != 40));
                }
                float w = five ? 5.0f : 1.0f;
                if (col >= cutoff) w *= 0.1f;   // dynamic weight 0.1 past cutoff
                acc = fmaf(d * d, w, acc);
            }
        }
    }

    // ---- block reduction, one double atomic per block ----
    #pragma unroll
    for (int o = 16; o > 0; o >>= 1)
        acc += __shfl_down_sync(0xffffffffu, acc, o);

    __shared__ float smem[8];
    if (lane == 0) smem[warp] = acc;
    __syncthreads();
    if (warp == 0) {
        float v = (lane < (int)(blockDim.x >> 5)) ? smem[lane] : 0.0f;
        #pragma unroll
        for (int o = 4; o > 0; o >>= 1)
            v += __shfl_down_sync(0xffffffffu, v, o);
        if (lane == 0) atomicAdd(&g_acc, (double)v);
    }
}

extern "C" void kernel_launch(void* const* d_in, const int* in_sizes, int n_in,
                              void* d_out, int out_size)
{
    const float* pred = (const float*)d_in[0];
    const float* targ = (const float*)d_in[1];
    const float* inp  = (const float*)d_in[2];
    float* out = (float*)d_out;

    const int B = in_sizes[0] / NCOLS;   // 500000

    zero_acc_kernel<<<1, 1>>>();
    // 148 SMs * 8 blocks/SM, 256 threads (8 warps) each -> persistent grid-stride
    wmse_kernel<<<1184, 256>>>(pred, targ, inp, B);
    finalize_kernel<<<1, 1>>>(out, (long long)B * NCOLS);
}